// round 3
// baseline (speedup 1.0000x reference)
#include <cuda_runtime.h>
#include <cstdint>

// RollerPooling forward.
// out[e][j] = (csum[e][min(j+w,128)] - csum[e][j]) / w,  w = 129 - target_size[e]
// One warp per edge-row. float4 coalesced load -> warp prefix scan -> shared
// csum (129 entries) -> windowed difference -> float4 coalesced store.

#define N_CH 128
#define WARPS_PER_BLOCK 8
#define THREADS (WARPS_PER_BLOCK * 32)

__global__ __launch_bounds__(THREADS)
void roller_pooling_kernel(const float* __restrict__ hidden,
                           const int* __restrict__ target_size,
                           float* __restrict__ out,
                           int n_edges) {
    __shared__ float sh[WARPS_PER_BLOCK][N_CH + 1];

    const int warp = threadIdx.x >> 5;
    const int lane = threadIdx.x & 31;
    const int e = blockIdx.x * WARPS_PER_BLOCK + warp;
    if (e >= n_edges) return;

    // Coalesced 512B row load (16B per lane).
    const float4* hp = reinterpret_cast<const float4*>(hidden + (size_t)e * N_CH);
    float4 v = hp[lane];

    // Per-lane partials and lane sum.
    float s = v.x + v.y + v.z + v.w;

    // Inclusive warp scan of lane sums.
    float inc = s;
    #pragma unroll
    for (int o = 1; o < 32; o <<= 1) {
        float t = __shfl_up_sync(0xffffffffu, inc, o);
        if (lane >= o) inc += t;
    }
    const float excl = inc - s;  // exclusive prefix at element 4*lane

    // Exclusive csum for this lane's 4 elements (kept in registers).
    const float c0 = excl;
    const float c1 = c0 + v.x;
    const float c2 = c1 + v.y;
    const float c3 = c2 + v.z;

    float* row = sh[warp];
    const int j = lane << 2;
    row[j + 0] = c0;
    row[j + 1] = c1;
    row[j + 2] = c2;
    row[j + 3] = c3;
    if (lane == 31) row[N_CH] = inc;  // csum[128] = row total
    __syncwarp();

    const int ts = target_size[e];       // broadcast load (same addr per warp)
    const int w = (N_CH + 1) - ts;       // window size in [1,128]
    const float invw = 1.0f / (float)w;

    float4 o4;
    o4.x = (row[min(j + 0 + w, N_CH)] - c0) * invw;
    o4.y = (row[min(j + 1 + w, N_CH)] - c1) * invw;
    o4.z = (row[min(j + 2 + w, N_CH)] - c2) * invw;
    o4.w = (row[min(j + 3 + w, N_CH)] - c3) * invw;

    reinterpret_cast<float4*>(out + (size_t)e * N_CH)[lane] = o4;
}

extern "C" void kernel_launch(void* const* d_in, const int* in_sizes, int n_in,
                              void* d_out, int out_size) {
    const float* hidden = (const float*)d_in[0];
    const int* target_size = (const int*)d_in[1];
    float* out = (float*)d_out;
    const int n_edges = in_sizes[1];  // target_size has one entry per edge

    const int blocks = (n_edges + WARPS_PER_BLOCK - 1) / WARPS_PER_BLOCK;
    roller_pooling_kernel<<<blocks, THREADS>>>(hidden, target_size, out, n_edges);
}

// round 4
// speedup vs baseline: 1.0910x; 1.0910x over previous
#include <cuda_runtime.h>
#include <cstdint>

// RollerPooling forward, shared-memory-free.
// out[e][j] = (csum[min(j+w,128)] - csum[j]) / w,  w = 129 - target_size[e].
// One warp per row. float4 load -> warp shuffle scan -> shuffle-based gather
// (w is warp-uniform: index 4*lane+k+w lives in register c_{(k+b)&3} of lane
// lane+q+carry, where w=4q+b) -> float4 store. Zero LDS/STS traffic.

#define N_CH 128
#define WARPS_PER_BLOCK 8
#define THREADS (WARPS_PER_BLOCK * 32)

__global__ __launch_bounds__(THREADS)
void roller_pooling_kernel(const float* __restrict__ hidden,
                           const int* __restrict__ target_size,
                           float* __restrict__ out,
                           int n_edges) {
    const int warp = threadIdx.x >> 5;
    const int lane = threadIdx.x & 31;
    const int e = blockIdx.x * WARPS_PER_BLOCK + warp;
    if (e >= n_edges) return;

    const unsigned m = 0xffffffffu;

    // Coalesced 512B row load (16B per lane).
    const float4* hp = reinterpret_cast<const float4*>(hidden + (size_t)e * N_CH);
    float4 v = hp[lane];

    // Lane sum + inclusive warp scan of lane sums.
    float s = v.x + v.y + v.z + v.w;
    float inc = s;
    #pragma unroll
    for (int o = 1; o < 32; o <<= 1) {
        float t = __shfl_up_sync(m, inc, o);
        if (lane >= o) inc += t;
    }
    const float excl = inc - s;

    // Exclusive csum at this lane's 4 elements (registers only).
    const float c0 = excl;
    const float c1 = c0 + v.x;
    const float c2 = c1 + v.y;
    const float c3 = c2 + v.z;

    const float total = __shfl_sync(m, inc, 31);   // csum[128]

    const int ts = target_size[e];                 // warp-broadcast load
    const int w = (N_CH + 1) - ts;                 // in [1,128], warp-uniform
    const int q = w >> 2;
    const int b = w & 3;
    const float invw = 1.0f / (float)w;

    // g_r = csum value with residue r gathered from lane + q (+1 if r < b).
    // srcLane = (4*lane + k + w) >> 2 exactly; shfl wraps mod 32 for
    // out-of-range lanes, which we override with the clamp below.
    const float g0 = __shfl_sync(m, c0, lane + q + (0 < b ? 1 : 0));
    const float g1 = __shfl_sync(m, c1, lane + q + (1 < b ? 1 : 0));
    const float g2 = __shfl_sync(m, c2, lane + q + (2 < b ? 1 : 0));
    const float g3 = __shfl_sync(m, c3, lane + q + (3 < b ? 1 : 0));

    // Permute: end-of-window csum for output k uses residue (k+b)&3.
    float e0, e1, e2, e3;
    switch (b) {   // warp-uniform branch
        case 0:  e0 = g0; e1 = g1; e2 = g2; e3 = g3; break;
        case 1:  e0 = g1; e1 = g2; e2 = g3; e3 = g0; break;
        case 2:  e0 = g2; e1 = g3; e2 = g0; e3 = g1; break;
        default: e0 = g3; e1 = g0; e2 = g1; e3 = g2; break;
    }

    // Clamp: indices past 128 read csum[128] = total.
    const int j = lane << 2;
    if (j + 0 + w >= N_CH) e0 = total;
    if (j + 1 + w >= N_CH) e1 = total;
    if (j + 2 + w >= N_CH) e2 = total;
    if (j + 3 + w >= N_CH) e3 = total;

    float4 o4;
    o4.x = (e0 - c0) * invw;
    o4.y = (e1 - c1) * invw;
    o4.z = (e2 - c2) * invw;
    o4.w = (e3 - c3) * invw;

    reinterpret_cast<float4*>(out + (size_t)e * N_CH)[lane] = o4;
}

extern "C" void kernel_launch(void* const* d_in, const int* in_sizes, int n_in,
                              void* d_out, int out_size) {
    const float* hidden = (const float*)d_in[0];
    const int* target_size = (const int*)d_in[1];
    float* out = (float*)d_out;
    const int n_edges = in_sizes[1];

    const int blocks = (n_edges + WARPS_PER_BLOCK - 1) / WARPS_PER_BLOCK;
    roller_pooling_kernel<<<blocks, THREADS>>>(hidden, target_size, out, n_edges);
}

// round 5
// speedup vs baseline: 1.2112x; 1.1101x over previous
#include <cuda_runtime.h>
#include <cstdint>

// RollerPooling forward, shared-memory-free, 2 rows per warp (front-batched
// loads for 2x memory-level parallelism).
// out[e][j] = (csum[min(j+w,128)] - csum[j]) / w,  w = 129 - target_size[e].
// Per row: float4 load -> warp shuffle scan -> shuffle gather (w warp-uniform:
// index 4*lane+k+w lives in register c_{(k+b)&3} of lane lane+q+carry, w=4q+b)
// -> float4 store.

#define N_CH 128
#define WARPS_PER_BLOCK 8
#define THREADS (WARPS_PER_BLOCK * 32)
#define ROWS_PER_WARP 2

__device__ __forceinline__ float4 roller_row(float4 v, int w, int lane) {
    const unsigned m = 0xffffffffu;

    // Lane sum + inclusive warp scan of lane sums.
    float s = v.x + v.y + v.z + v.w;
    float inc = s;
    #pragma unroll
    for (int o = 1; o < 32; o <<= 1) {
        float t = __shfl_up_sync(m, inc, o);
        if (lane >= o) inc += t;
    }
    const float excl = inc - s;

    // Exclusive csum at this lane's 4 elements (registers only).
    const float c0 = excl;
    const float c1 = c0 + v.x;
    const float c2 = c1 + v.y;
    const float c3 = c2 + v.z;

    const float total = __shfl_sync(m, inc, 31);   // csum[128]

    const int q = w >> 2;
    const int b = w & 3;
    const float invw = 1.0f / (float)w;

    // Gather csum[4*lane + k + w] via shuffles (srcLane = (4*lane+k+w)>>2;
    // mod-32 wrap for OOB lanes is overridden by the clamp below).
    const float g0 = __shfl_sync(m, c0, lane + q + (0 < b ? 1 : 0));
    const float g1 = __shfl_sync(m, c1, lane + q + (1 < b ? 1 : 0));
    const float g2 = __shfl_sync(m, c2, lane + q + (2 < b ? 1 : 0));
    const float g3 = __shfl_sync(m, c3, lane + q + (3 < b ? 1 : 0));

    // Permute: end-of-window csum for output k uses residue (k+b)&3.
    float e0, e1, e2, e3;
    switch (b) {   // warp-uniform branch
        case 0:  e0 = g0; e1 = g1; e2 = g2; e3 = g3; break;
        case 1:  e0 = g1; e1 = g2; e2 = g3; e3 = g0; break;
        case 2:  e0 = g2; e1 = g3; e2 = g0; e3 = g1; break;
        default: e0 = g3; e1 = g0; e2 = g1; e3 = g2; break;
    }

    // Clamp: window ends past 128 read csum[128] = total.
    const int j = lane << 2;
    if (j + 0 + w >= N_CH) e0 = total;
    if (j + 1 + w >= N_CH) e1 = total;
    if (j + 2 + w >= N_CH) e2 = total;
    if (j + 3 + w >= N_CH) e3 = total;

    float4 o4;
    o4.x = (e0 - c0) * invw;
    o4.y = (e1 - c1) * invw;
    o4.z = (e2 - c2) * invw;
    o4.w = (e3 - c3) * invw;
    return o4;
}

__global__ __launch_bounds__(THREADS)
void roller_pooling_kernel(const float* __restrict__ hidden,
                           const int* __restrict__ target_size,
                           float* __restrict__ out,
                           int n_edges) {
    const int warp = threadIdx.x >> 5;
    const int lane = threadIdx.x & 31;
    const int e0 = (blockIdx.x * WARPS_PER_BLOCK + warp) * ROWS_PER_WARP;
    if (e0 >= n_edges) return;

    const bool hasB = (e0 + 1) < n_edges;

    // Front-batch all global loads: 2x LDG.128 + 2x LDG.32 in flight
    // before any dependent compute.
    const float4* hpA = reinterpret_cast<const float4*>(hidden + (size_t)e0 * N_CH);
    const float4* hpB = reinterpret_cast<const float4*>(hidden + (size_t)(e0 + 1) * N_CH);
    float4 vA = hpA[lane];
    float4 vB = hasB ? hpB[lane] : make_float4(0.f, 0.f, 0.f, 0.f);
    const int tsA = target_size[e0];
    const int tsB = hasB ? target_size[e0 + 1] : 1;

    const int wA = (N_CH + 1) - tsA;
    const int wB = (N_CH + 1) - tsB;

    float4 oA = roller_row(vA, wA, lane);
    reinterpret_cast<float4*>(out + (size_t)e0 * N_CH)[lane] = oA;

    if (hasB) {
        float4 oB = roller_row(vB, wB, lane);
        reinterpret_cast<float4*>(out + (size_t)(e0 + 1) * N_CH)[lane] = oB;
    }
}

extern "C" void kernel_launch(void* const* d_in, const int* in_sizes, int n_in,
                              void* d_out, int out_size) {
    const float* hidden = (const float*)d_in[0];
    const int* target_size = (const int*)d_in[1];
    float* out = (float*)d_out;
    const int n_edges = in_sizes[1];

    const int rows_per_block = WARPS_PER_BLOCK * ROWS_PER_WARP;
    const int blocks = (n_edges + rows_per_block - 1) / rows_per_block;
    roller_pooling_kernel<<<blocks, THREADS>>>(hidden, target_size, out, n_edges);
}